// round 8
// baseline (speedup 1.0000x reference)
#include <cuda_runtime.h>
#include <cstdint>

// out = x * (1 - mask), mask broadcasts over C=3.
// x:    [B=64, C=3, H=512, W=512] f32
// mask: [B=64, 1,   H=512, W=512] f32, exactly 0/1 in large rectangles.
//
// R5 trick kept: where mask==1 the output is exactly 0.0f -> skip x loads.
// R6: 2 float4 positions per thread (MLP 8, half the blocks) to recover
// DRAM saturation lost to the lighter masked-region blocks.

static constexpr int Cc = 3;
static constexpr int HW = 512 * 512;
static constexpr int HW4 = HW / 4;        // 65536 float4 per plane
static constexpr int THREADS = 256;
static constexpr int VPT = 2;             // float4 positions per thread

__device__ __forceinline__ float4 blend(float4 xv, float4 w) {
    return make_float4(xv.x * w.x, xv.y * w.y, xv.z * w.z, xv.w * w.w);
}

__global__ __launch_bounds__(THREADS, 8)
void random_mask_kernel(const float4* __restrict__ x,
                        const float4* __restrict__ mask,
                        float4* __restrict__ out) {
    const int b = blockIdx.y;                                     // batch
    const int v = (blockIdx.x * THREADS + threadIdx.x) * VPT;     // 0..HW4-2

    const long long mi = (long long)b * HW4 + v;
    const long long x0 = (long long)(b * Cc) * HW4 + v;

    // Both mask vectors first.
    const float4 m0 = mask[mi];
    const float4 m1 = mask[mi + 1];

    const bool fm0 = (m0.x == 1.0f) & (m0.y == 1.0f) & (m0.z == 1.0f) & (m0.w == 1.0f);
    const bool fm1 = (m1.x == 1.0f) & (m1.y == 1.0f) & (m1.z == 1.0f) & (m1.w == 1.0f);

    if (fm0 & fm1) {
        const float4 z = make_float4(0.0f, 0.0f, 0.0f, 0.0f);
        out[x0]               = z;
        out[x0 + 1]           = z;
        out[x0 + HW4]         = z;
        out[x0 + HW4 + 1]     = z;
        out[x0 + 2 * HW4]     = z;
        out[x0 + 2 * HW4 + 1] = z;
        return;
    }

    // Issue all 6 x loads up front for maximum MLP.
    const float4 a0 = x[x0];
    const float4 a1 = x[x0 + 1];
    const float4 b0 = x[x0 + HW4];
    const float4 b1 = x[x0 + HW4 + 1];
    const float4 c0 = x[x0 + 2 * HW4];
    const float4 c1 = x[x0 + 2 * HW4 + 1];

    const float4 w0 = make_float4(1.0f - m0.x, 1.0f - m0.y, 1.0f - m0.z, 1.0f - m0.w);
    const float4 w1 = make_float4(1.0f - m1.x, 1.0f - m1.y, 1.0f - m1.z, 1.0f - m1.w);

    out[x0]               = blend(a0, w0);
    out[x0 + 1]           = blend(a1, w1);
    out[x0 + HW4]         = blend(b0, w0);
    out[x0 + HW4 + 1]     = blend(b1, w1);
    out[x0 + 2 * HW4]     = blend(c0, w0);
    out[x0 + 2 * HW4 + 1] = blend(c1, w1);
}

extern "C" void kernel_launch(void* const* d_in, const int* in_sizes, int n_in,
                              void* d_out, int out_size) {
    const float4* x    = (const float4*)d_in[0];
    const float4* mask = (const float4*)d_in[1];
    float4* out        = (float4*)d_out;

    const int B = in_sizes[1] / HW;                   // 64
    dim3 grid(HW4 / (THREADS * VPT), B);              // (128, 64)
    random_mask_kernel<<<grid, THREADS>>>(x, mask, out);
}

// round 9
// speedup vs baseline: 1.0666x; 1.0666x over previous
#include <cuda_runtime.h>
#include <cstdint>

// out = x * (1 - mask), mask broadcasts over C=3.
// x:    [B=64, C=3, H=512, W=512] f32
// mask: [B=64, 1,   H=512, W=512] f32, exactly 0/1 in large rectangles.
//
// R5 trick: where mask==1 output is exactly 0.0f -> skip the x loads.
// R8: 2 positions per thread with THREAD-INTERLEAVED stride (pos and
// pos+THREADS) so every LDG/STG stays perfectly warp-coalesced (4 lines
// per warp-load), unlike R6's adjacent-pair layout (8 lines). MLP=8.

static constexpr int Cc = 3;
static constexpr int HW = 512 * 512;
static constexpr int HW4 = HW / 4;        // 65536 float4 per plane
static constexpr int THREADS = 256;
static constexpr int VPT = 2;             // positions per thread

__device__ __forceinline__ float4 blend(float4 xv, float4 m) {
    return make_float4(xv.x * (1.0f - m.x), xv.y * (1.0f - m.y),
                       xv.z * (1.0f - m.z), xv.w * (1.0f - m.w));
}

__device__ __forceinline__ bool allone(float4 m) {
    return (m.x == 1.0f) & (m.y == 1.0f) & (m.z == 1.0f) & (m.w == 1.0f);
}

__global__ __launch_bounds__(THREADS, 8)
void random_mask_kernel(const float4* __restrict__ x,
                        const float4* __restrict__ mask,
                        float4* __restrict__ out) {
    const int b  = blockIdx.y;                                      // batch
    const int v0 = blockIdx.x * (THREADS * VPT) + threadIdx.x;      // pos 0
    const int v1 = v0 + THREADS;                                    // pos 1

    const long long mbase = (long long)b * HW4;
    const long long xbase = (long long)(b * Cc) * HW4;

    const float4 m0 = mask[mbase + v0];
    const float4 m1 = mask[mbase + v1];

    const bool fm0 = allone(m0);
    const bool fm1 = allone(m1);

    const long long p0 = xbase + v0;
    const long long p1 = xbase + v1;
    const float4 z = make_float4(0.0f, 0.0f, 0.0f, 0.0f);

    if (fm0 & fm1) {
        out[p0] = z; out[p0 + HW4] = z; out[p0 + 2 * HW4] = z;
        out[p1] = z; out[p1 + HW4] = z; out[p1 + 2 * HW4] = z;
        return;
    }

    if (!fm0 & !fm1) {
        // Both live: issue all 6 loads up front (MLP 8 incl. masks).
        const float4 a0 = x[p0];
        const float4 a1 = x[p1];
        const float4 b0 = x[p0 + HW4];
        const float4 b1 = x[p1 + HW4];
        const float4 c0 = x[p0 + 2 * HW4];
        const float4 c1 = x[p1 + 2 * HW4];
        out[p0]           = blend(a0, m0);
        out[p1]           = blend(a1, m1);
        out[p0 + HW4]     = blend(b0, m0);
        out[p1 + HW4]     = blend(b1, m1);
        out[p0 + 2 * HW4] = blend(c0, m0);
        out[p1 + 2 * HW4] = blend(c1, m1);
        return;
    }

    // Mixed: exactly one position is fully masked.
    const long long pl = fm0 ? p1 : p0;      // live position
    const long long pm = fm0 ? p0 : p1;      // masked position
    const float4    ml = fm0 ? m1 : m0;

    const float4 a = x[pl];
    const float4 bb = x[pl + HW4];
    const float4 c = x[pl + 2 * HW4];

    out[pm] = z; out[pm + HW4] = z; out[pm + 2 * HW4] = z;
    out[pl]           = blend(a, ml);
    out[pl + HW4]     = blend(bb, ml);
    out[pl + 2 * HW4] = blend(c, ml);
}

extern "C" void kernel_launch(void* const* d_in, const int* in_sizes, int n_in,
                              void* d_out, int out_size) {
    const float4* x    = (const float4*)d_in[0];
    const float4* mask = (const float4*)d_in[1];
    float4* out        = (float4*)d_out;

    const int B = in_sizes[1] / HW;                   // 64
    dim3 grid(HW4 / (THREADS * VPT), B);              // (128, 64)
    random_mask_kernel<<<grid, THREADS>>>(x, mask, out);
}